// round 2
// baseline (speedup 1.0000x reference)
#include <cuda_runtime.h>

#define NNODES 100000
#define NEDGES 1600000

typedef unsigned long long ull;

// ---- scratch (device globals; no allocation allowed) ----
__device__ int   g_counts[NNODES];
__device__ int   g_fill[NNODES];
__device__ int   g_rowptr[NNODES + 1];
__device__ int2  g_edge[NEDGES];          // {src, __float_as_int(w)}
__device__ float g_support[(size_t)NNODES * 64];
__device__ float g_h[(size_t)NNODES * 64];

// ---------------------------------------------------------------- f32x2 helpers
__device__ __forceinline__ void ffma2(ull& d, ull a, ull b) {
    asm("fma.rn.f32x2 %0, %1, %2, %0;" : "+l"(d) : "l"(a), "l"(b));
}
__device__ __forceinline__ ull pack2(float x, float y) {
    ull r; asm("mov.b64 %0, {%1, %2};" : "=l"(r) : "f"(x), "f"(y)); return r;
}
__device__ __forceinline__ void unpack2(ull v, float& lo, float& hi) {
    asm("mov.b64 {%0, %1}, %2;" : "=f"(lo), "=f"(hi) : "l"(v));
}

// ---------------------------------------------------------------- CSR build
__global__ void hist_kernel(const int* __restrict__ tgt) {
    int e = blockIdx.x * blockDim.x + threadIdx.x;
    if (e < NEDGES) atomicAdd(&g_counts[tgt[e]], 1);
}

// single-block exclusive scan over 100k counts -> rowptr; also zeroes g_fill
__global__ void scan_kernel() {
    __shared__ int sums[1024];
    int t = threadIdx.x;
    const int C = (NNODES + 1023) >> 10;   // 98
    int lo = t * C;
    int hi = lo + C; if (hi > NNODES) hi = NNODES;
    int s = 0;
    for (int i = lo; i < hi; i++) s += g_counts[i];
    sums[t] = s;
    __syncthreads();
    for (int off = 1; off < 1024; off <<= 1) {
        int v = sums[t];
        int add = (t >= off) ? sums[t - off] : 0;
        __syncthreads();
        sums[t] = v + add;
        __syncthreads();
    }
    int run = (t == 0) ? 0 : sums[t - 1];
    for (int i = lo; i < hi; i++) {
        g_rowptr[i] = run;
        g_fill[i] = 0;
        run += g_counts[i];
    }
    if (hi == NNODES) g_rowptr[NNODES] = run;   // == NEDGES (idempotent writers)
}

__global__ void scatter_kernel(const int* __restrict__ src,
                               const int* __restrict__ tgt,
                               const float* __restrict__ w) {
    int e = blockIdx.x * blockDim.x + threadIdx.x;
    if (e >= NEDGES) return;
    int t = tgt[e];
    int pos = g_rowptr[t] + atomicAdd(&g_fill[t], 1);
    int2 pk; pk.x = src[e]; pk.y = __float_as_int(w[e]);
    g_edge[pos] = pk;                     // single 8B store
}

// ---------------------------------------------------------------- dense GEMM
// Y[nrows,M] = X[nrows,K] @ W[K,M].  64-row tile, 4 rows x 8 cols per thread,
// packed f32x2 accumulators (FFMA2): 16 packed FMAs per k per thread.
template <int K, int M>
__global__ void gemm2_kernel(const float* __restrict__ X,
                             const float* __restrict__ W,
                             float* __restrict__ Y, int nrows) {
    extern __shared__ float sm[];
    float* Ws = sm;               // K*M
    float* Xs = sm + K * M;       // 64*(K+4), padded vs bank conflicts
    const int nthr = blockDim.x * blockDim.y;
    const int tid  = threadIdx.y * blockDim.x + threadIdx.x;

    for (int i = tid; i < K * M / 4; i += nthr)
        ((float4*)Ws)[i] = ((const float4*)W)[i];

    const int rowBase = blockIdx.x * 64;
    int rlim = nrows - rowBase; if (rlim > 64) rlim = 64;
    const int KV = K / 4;
    for (int i = tid; i < rlim * KV; i += nthr) {
        int r = i / KV, c = i - r * KV;
        float4 v = ((const float4*)X)[(size_t)(rowBase + r) * KV + c];
        *(float4*)&Xs[r * (K + 4) + c * 4] = v;
    }
    __syncthreads();

    const int j  = threadIdx.x * 8;   // blockDim.x = M/8
    const int r0 = threadIdx.y * 4;   // blockDim.y = 16 -> 64 rows
    ull acc[4][4];
#pragma unroll
    for (int r = 0; r < 4; r++)
#pragma unroll
        for (int p = 0; p < 4; p++) acc[r][p] = 0ull;

#pragma unroll 8
    for (int k = 0; k < K; k++) {
        ulonglong2 wa = *(const ulonglong2*)&Ws[k * M + j];       // cols j..j+3
        ulonglong2 wb = *(const ulonglong2*)&Ws[k * M + j + 4];   // cols j+4..j+7
#pragma unroll
        for (int r = 0; r < 4; r++) {
            float xv = Xs[(r0 + r) * (K + 4) + k];
            ull   xp = pack2(xv, xv);
            ffma2(acc[r][0], xp, wa.x);
            ffma2(acc[r][1], xp, wa.y);
            ffma2(acc[r][2], xp, wb.x);
            ffma2(acc[r][3], xp, wb.y);
        }
    }

#pragma unroll
    for (int r = 0; r < 4; r++) {
        int row = rowBase + r0 + r;
        if (row < nrows) {
            float o[8];
#pragma unroll
            for (int p = 0; p < 4; p++) unpack2(acc[r][p], o[2 * p], o[2 * p + 1]);
            float4 v0; v0.x = o[0]; v0.y = o[1]; v0.z = o[2]; v0.w = o[3];
            float4 v1; v1.x = o[4]; v1.y = o[5]; v1.z = o[6]; v1.w = o[7];
            *(float4*)&Y[(size_t)row * M + j]     = v0;
            *(float4*)&Y[(size_t)row * M + j + 4] = v1;
        }
    }
}

// ----------------------------------------------------- sparse aggregation, M=64
// warp per node; lane owns features (lane, lane+32). Fused bias+relu(+residual).
__global__ void agg64_kernel(const float* __restrict__ sup,
                             const float* __restrict__ bias,
                             float* hout, const float* resid, int has_resid) {
    int gw   = (blockIdx.x * blockDim.x + threadIdx.x) >> 5;
    int lane = threadIdx.x & 31;
    if (gw >= NNODES) return;
    int e   = g_rowptr[gw];
    int end = g_rowptr[gw + 1];
    float a0 = 0.f, a1 = 0.f;
    for (; e + 4 <= end; e += 4) {
        int2 e0 = g_edge[e], e1 = g_edge[e + 1], e2 = g_edge[e + 2], e3 = g_edge[e + 3];
        const float* p0 = sup + (size_t)e0.x * 64;
        const float* p1 = sup + (size_t)e1.x * 64;
        const float* p2 = sup + (size_t)e2.x * 64;
        const float* p3 = sup + (size_t)e3.x * 64;
        float x0 = p0[lane], y0 = p0[lane + 32];
        float x1 = p1[lane], y1 = p1[lane + 32];
        float x2 = p2[lane], y2 = p2[lane + 32];
        float x3 = p3[lane], y3 = p3[lane + 32];
        float w0 = __int_as_float(e0.y), w1 = __int_as_float(e1.y);
        float w2 = __int_as_float(e2.y), w3 = __int_as_float(e3.y);
        a0 = fmaf(x0, w0, a0); a1 = fmaf(y0, w0, a1);
        a0 = fmaf(x1, w1, a0); a1 = fmaf(y1, w1, a1);
        a0 = fmaf(x2, w2, a0); a1 = fmaf(y2, w2, a1);
        a0 = fmaf(x3, w3, a0); a1 = fmaf(y3, w3, a1);
    }
    for (; e < end; e++) {
        int2 ed = g_edge[e];
        const float* p = sup + (size_t)ed.x * 64;
        float w = __int_as_float(ed.y);
        a0 = fmaf(p[lane], w, a0);
        a1 = fmaf(p[lane + 32], w, a1);
    }
    a0 = fmaxf(a0 + bias[lane], 0.f);
    a1 = fmaxf(a1 + bias[lane + 32], 0.f);
    size_t base = (size_t)gw * 64;
    if (has_resid) {               // resid may alias hout: same-element RMW only
        a0 += resid[base + lane];
        a1 += resid[base + lane + 32];
    }
    hout[base + lane]      = a0;
    hout[base + lane + 32] = a1;
}

// ------------------------------------------- sparse aggregation + log_softmax, M=40
__global__ void agg40_kernel(const float* __restrict__ sup,
                             const float* __restrict__ bias,
                             float* __restrict__ out) {
    int gw   = (blockIdx.x * blockDim.x + threadIdx.x) >> 5;
    int lane = threadIdx.x & 31;
    if (gw >= NNODES) return;
    int e   = g_rowptr[gw];
    int end = g_rowptr[gw + 1];
    float a0 = 0.f, a1 = 0.f;
    for (; e + 4 <= end; e += 4) {
        int2 e0 = g_edge[e], e1 = g_edge[e + 1], e2 = g_edge[e + 2], e3 = g_edge[e + 3];
        const float* p0 = sup + (size_t)e0.x * 40;
        const float* p1 = sup + (size_t)e1.x * 40;
        const float* p2 = sup + (size_t)e2.x * 40;
        const float* p3 = sup + (size_t)e3.x * 40;
        float w0 = __int_as_float(e0.y), w1 = __int_as_float(e1.y);
        float w2 = __int_as_float(e2.y), w3 = __int_as_float(e3.y);
        a0 = fmaf(p0[lane], w0, a0);
        a0 = fmaf(p1[lane], w1, a0);
        a0 = fmaf(p2[lane], w2, a0);
        a0 = fmaf(p3[lane], w3, a0);
        if (lane < 8) {
            a1 = fmaf(p0[32 + lane], w0, a1);
            a1 = fmaf(p1[32 + lane], w1, a1);
            a1 = fmaf(p2[32 + lane], w2, a1);
            a1 = fmaf(p3[32 + lane], w3, a1);
        }
    }
    for (; e < end; e++) {
        int2 ed = g_edge[e];
        const float* p = sup + (size_t)ed.x * 40;
        float w = __int_as_float(ed.y);
        a0 = fmaf(p[lane], w, a0);
        if (lane < 8) a1 = fmaf(p[32 + lane], w, a1);
    }
    a0 += bias[lane];
    if (lane < 8) a1 += bias[32 + lane];

    // log_softmax over 40 features distributed over the warp
    float m = a0;
    if (lane < 8) m = fmaxf(m, a1);
#pragma unroll
    for (int o = 16; o; o >>= 1) m = fmaxf(m, __shfl_xor_sync(0xffffffffu, m, o));
    float ssum = __expf(a0 - m) + ((lane < 8) ? __expf(a1 - m) : 0.f);
#pragma unroll
    for (int o = 16; o; o >>= 1) ssum += __shfl_xor_sync(0xffffffffu, ssum, o);
    float L = m + __logf(ssum);

    out[(size_t)gw * 40 + lane] = a0 - L;
    if (lane < 8) out[(size_t)gw * 40 + 32 + lane] = a1 - L;
}

// ---------------------------------------------------------------- launch
static cudaStream_t s_side = nullptr;
static cudaEvent_t  s_evFork = nullptr, s_evJoin = nullptr;

extern "C" void kernel_launch(void* const* d_in, const int* in_sizes, int n_in,
                              void* d_out, int out_size) {
    const float* x   = (const float*)d_in[0];
    const int*   src = (const int*)d_in[1];
    const int*   tgt = (const int*)d_in[2];
    const float* mw  = (const float*)d_in[3];
    const float* W0  = (const float*)d_in[4];  const float* b0 = (const float*)d_in[5];
    const float* W1  = (const float*)d_in[6];  const float* b1 = (const float*)d_in[7];
    const float* W2  = (const float*)d_in[8];  const float* b2 = (const float*)d_in[9];
    const float* W3  = (const float*)d_in[10]; const float* b3 = (const float*)d_in[11];
    float* out = (float*)d_out;

    if (!s_side) {   // one-time host-side resource init (outside capture on run 1)
        cudaStreamCreateWithFlags(&s_side, cudaStreamNonBlocking);
        cudaEventCreateWithFlags(&s_evFork, cudaEventDisableTiming);
        cudaEventCreateWithFlags(&s_evJoin, cudaEventDisableTiming);
        const int S0 = (128 * 64 + 64 * (128 + 4)) * 4;  // 66560
        cudaFuncSetAttribute(gemm2_kernel<128, 64>, cudaFuncAttributeMaxDynamicSharedMemorySize, S0);
    }

    const int S0 = (128 * 64 + 64 * (128 + 4)) * 4;  // 66560
    const int S1 = (64 * 64 + 64 * (64 + 4)) * 4;    // 33792
    const int S3 = (64 * 40 + 64 * (64 + 4)) * 4;    // 27648

    void* p;
    cudaGetSymbolAddress(&p, g_support); float* sup = (float*)p;
    cudaGetSymbolAddress(&p, g_h);       float* h   = (float*)p;
    void* pcnt; cudaGetSymbolAddress(&pcnt, g_counts);

    const int gblocks = (NNODES + 63) / 64;
    const int ablocks = ((NNODES * 32) + 255) / 256;

    // ---- fork: CSR build on side stream, overlapped with GEMM-0 ----
    cudaEventRecord(s_evFork, 0);
    cudaStreamWaitEvent(s_side, s_evFork, 0);
    cudaMemsetAsync(pcnt, 0, NNODES * sizeof(int), s_side);
    hist_kernel<<<(NEDGES + 255) / 256, 256, 0, s_side>>>(tgt);
    scan_kernel<<<1, 1024, 0, s_side>>>();
    scatter_kernel<<<(NEDGES + 255) / 256, 256, 0, s_side>>>(src, tgt, mw);
    cudaEventRecord(s_evJoin, s_side);

    // layer 0 GEMM runs concurrently with the CSR build
    gemm2_kernel<128, 64><<<gblocks, dim3(8, 16), S0>>>(x, W0, sup, NNODES);
    cudaStreamWaitEvent(0, s_evJoin, 0);   // join before first aggregation

    // layer 0: h = relu(A @ (x W0) + b0)
    agg64_kernel<<<ablocks, 256>>>(sup, b0, h, nullptr, 0);
    // layer 1: h = relu(A @ (h W1) + b1) + h
    gemm2_kernel<64, 64><<<gblocks, dim3(8, 16), S1>>>(h, W1, sup, NNODES);
    agg64_kernel<<<ablocks, 256>>>(sup, b1, h, h, 1);
    // layer 2
    gemm2_kernel<64, 64><<<gblocks, dim3(8, 16), S1>>>(h, W2, sup, NNODES);
    agg64_kernel<<<ablocks, 256>>>(sup, b2, h, h, 1);
    // layer 3: out = log_softmax(A @ (h W3) + b3)
    gemm2_kernel<64, 40><<<gblocks, dim3(5, 16), S3>>>(h, W3, sup, NNODES);
    agg40_kernel<<<ablocks, 256>>>(sup, b3, out);
}

// round 3
// speedup vs baseline: 1.3458x; 1.3458x over previous
#include <cuda_runtime.h>

#define NNODES 100000
#define NEDGES 1600000

typedef unsigned long long ull;

// ---- scratch (device globals; no allocation allowed) ----
__device__ int   g_counts[NNODES];
__device__ int   g_fill[NNODES];
__device__ int   g_rowptr[NNODES + 1];
__device__ int2  g_edge[NEDGES];          // {src, __float_as_int(w)}
__device__ float g_support[(size_t)NNODES * 64];
__device__ float g_h[(size_t)NNODES * 64];

// ---------------------------------------------------------------- f32x2 helpers
__device__ __forceinline__ void ffma2(ull& d, ull a, ull b) {
    asm("fma.rn.f32x2 %0, %1, %2, %0;" : "+l"(d) : "l"(a), "l"(b));
}
__device__ __forceinline__ ull pack2(float x, float y) {
    ull r; asm("mov.b64 %0, {%1, %2};" : "=l"(r) : "f"(x), "f"(y)); return r;
}
__device__ __forceinline__ void unpack2(ull v, float& lo, float& hi) {
    asm("mov.b64 {%0, %1}, %2;" : "=f"(lo), "=f"(hi) : "l"(v));
}

// ---------------------------------------------------------------- CSR build
__global__ void zero_counts_kernel() {
    int i = blockIdx.x * blockDim.x + threadIdx.x;
    if (i < NNODES) g_counts[i] = 0;
}

__global__ void hist_kernel(const int* __restrict__ tgt) {
    int e = blockIdx.x * blockDim.x + threadIdx.x;
    if (e < NEDGES) atomicAdd(&g_counts[tgt[e]], 1);
}

// single-block exclusive scan over 100k counts -> rowptr; also zeroes g_fill
__global__ void scan_kernel() {
    __shared__ int sums[1024];
    int t = threadIdx.x;
    const int C = (NNODES + 1023) >> 10;   // 98
    int lo = t * C;
    int hi = lo + C; if (hi > NNODES) hi = NNODES;
    int s = 0;
    for (int i = lo; i < hi; i++) s += g_counts[i];
    sums[t] = s;
    __syncthreads();
    for (int off = 1; off < 1024; off <<= 1) {
        int v = sums[t];
        int add = (t >= off) ? sums[t - off] : 0;
        __syncthreads();
        sums[t] = v + add;
        __syncthreads();
    }
    int run = (t == 0) ? 0 : sums[t - 1];
    for (int i = lo; i < hi; i++) {
        g_rowptr[i] = run;
        g_fill[i] = 0;
        run += g_counts[i];
    }
    if (hi == NNODES) g_rowptr[NNODES] = run;   // == NEDGES (idempotent writers)
}

__global__ void scatter_kernel(const int* __restrict__ src,
                               const int* __restrict__ tgt,
                               const float* __restrict__ w) {
    int e = blockIdx.x * blockDim.x + threadIdx.x;
    if (e >= NEDGES) return;
    int t = tgt[e];
    int pos = g_rowptr[t] + atomicAdd(&g_fill[t], 1);
    int2 pk; pk.x = src[e]; pk.y = __float_as_int(w[e]);
    g_edge[pos] = pk;                     // single 8B store
}

// ---------------------------------------------------------------- dense GEMM
// Y[nrows,M] = X[nrows,K] @ W[K,M].  64-row tile, 4 rows x 4 cols per thread
// (256 threads), FFMA2 packed over the K axis:
//   acc2[r][c] += {x_k, x_{k+1}} * {W[k][c], W[k+1][c]}
// W is stored k-interleaved in smem (ull per (k-pair, col)), so both operands
// are single aligned LDS.64/128 loads — no packing MOVs in the inner loop.
template <int K, int M>
__global__ void gemm3_kernel(const float* __restrict__ X,
                             const float* __restrict__ W,
                             float* __restrict__ Y, int nrows) {
    extern __shared__ float sm[];
    ull*   Wp = (ull*)sm;                  // [K/2][M] packed k-pairs, K*M*4 bytes
    float* Xs = sm + K * M;                // 64*(K+4), padded vs bank conflicts
    const int nthr = blockDim.x * blockDim.y;
    const int tid  = threadIdx.y * blockDim.x + threadIdx.x;

    // build k-interleaved W tile: Wp[k2*M + j] = {W[2k2][j], W[2k2+1][j]}
    for (int i = tid; i < (K / 2) * M; i += nthr) {
        int k2 = i / M, j = i - k2 * M;
        Wp[i] = pack2(W[(2 * k2) * M + j], W[(2 * k2 + 1) * M + j]);
    }

    const int rowBase = blockIdx.x * 64;
    int rlim = nrows - rowBase; if (rlim > 64) rlim = 64;
    const int KV = K / 4;
    for (int i = tid; i < rlim * KV; i += nthr) {
        int r = i / KV, c = i - r * KV;
        float4 v = ((const float4*)X)[(size_t)(rowBase + r) * KV + c];
        *(float4*)&Xs[r * (K + 4) + c * 4] = v;
    }
    __syncthreads();

    const int j  = threadIdx.x * 4;   // blockDim.x = M/4
    const int r0 = threadIdx.y * 4;   // blockDim.y = 16 -> 64 rows
    ull acc[4][4];
#pragma unroll
    for (int r = 0; r < 4; r++)
#pragma unroll
        for (int c = 0; c < 4; c++) acc[r][c] = 0ull;

#pragma unroll 8
    for (int k2 = 0; k2 < K / 2; k2++) {
        ulonglong2 wA = *(const ulonglong2*)&Wp[k2 * M + j];       // cols j, j+1
        ulonglong2 wB = *(const ulonglong2*)&Wp[k2 * M + j + 2];   // cols j+2, j+3
        ull xp0 = *(const ull*)&Xs[(r0 + 0) * (K + 4) + 2 * k2];
        ull xp1 = *(const ull*)&Xs[(r0 + 1) * (K + 4) + 2 * k2];
        ull xp2 = *(const ull*)&Xs[(r0 + 2) * (K + 4) + 2 * k2];
        ull xp3 = *(const ull*)&Xs[(r0 + 3) * (K + 4) + 2 * k2];
        ffma2(acc[0][0], xp0, wA.x); ffma2(acc[0][1], xp0, wA.y);
        ffma2(acc[0][2], xp0, wB.x); ffma2(acc[0][3], xp0, wB.y);
        ffma2(acc[1][0], xp1, wA.x); ffma2(acc[1][1], xp1, wA.y);
        ffma2(acc[1][2], xp1, wB.x); ffma2(acc[1][3], xp1, wB.y);
        ffma2(acc[2][0], xp2, wA.x); ffma2(acc[2][1], xp2, wA.y);
        ffma2(acc[2][2], xp2, wB.x); ffma2(acc[2][3], xp2, wB.y);
        ffma2(acc[3][0], xp3, wA.x); ffma2(acc[3][1], xp3, wA.y);
        ffma2(acc[3][2], xp3, wB.x); ffma2(acc[3][3], xp3, wB.y);
    }

#pragma unroll
    for (int r = 0; r < 4; r++) {
        int row = rowBase + r0 + r;
        if (row < nrows) {
            float4 o;
            float lo, hi;
            unpack2(acc[r][0], lo, hi); o.x = lo + hi;
            unpack2(acc[r][1], lo, hi); o.y = lo + hi;
            unpack2(acc[r][2], lo, hi); o.z = lo + hi;
            unpack2(acc[r][3], lo, hi); o.w = lo + hi;
            *(float4*)&Y[(size_t)row * M + j] = o;
        }
    }
}

// ----------------------------------------------------- sparse aggregation, M=64
// warp per node; lane owns features (lane, lane+32). Fused bias+relu(+residual).
__global__ void agg64_kernel(const float* __restrict__ sup,
                             const float* __restrict__ bias,
                             float* hout, const float* resid, int has_resid) {
    int gw   = (blockIdx.x * blockDim.x + threadIdx.x) >> 5;
    int lane = threadIdx.x & 31;
    if (gw >= NNODES) return;
    int e   = g_rowptr[gw];
    int end = g_rowptr[gw + 1];
    float a0 = 0.f, a1 = 0.f;
    for (; e + 4 <= end; e += 4) {
        int2 e0 = g_edge[e], e1 = g_edge[e + 1], e2 = g_edge[e + 2], e3 = g_edge[e + 3];
        const float* p0 = sup + (size_t)e0.x * 64;
        const float* p1 = sup + (size_t)e1.x * 64;
        const float* p2 = sup + (size_t)e2.x * 64;
        const float* p3 = sup + (size_t)e3.x * 64;
        float x0 = p0[lane], y0 = p0[lane + 32];
        float x1 = p1[lane], y1 = p1[lane + 32];
        float x2 = p2[lane], y2 = p2[lane + 32];
        float x3 = p3[lane], y3 = p3[lane + 32];
        float w0 = __int_as_float(e0.y), w1 = __int_as_float(e1.y);
        float w2 = __int_as_float(e2.y), w3 = __int_as_float(e3.y);
        a0 = fmaf(x0, w0, a0); a1 = fmaf(y0, w0, a1);
        a0 = fmaf(x1, w1, a0); a1 = fmaf(y1, w1, a1);
        a0 = fmaf(x2, w2, a0); a1 = fmaf(y2, w2, a1);
        a0 = fmaf(x3, w3, a0); a1 = fmaf(y3, w3, a1);
    }
    for (; e < end; e++) {
        int2 ed = g_edge[e];
        const float* p = sup + (size_t)ed.x * 64;
        float w = __int_as_float(ed.y);
        a0 = fmaf(p[lane], w, a0);
        a1 = fmaf(p[lane + 32], w, a1);
    }
    a0 = fmaxf(a0 + bias[lane], 0.f);
    a1 = fmaxf(a1 + bias[lane + 32], 0.f);
    size_t base = (size_t)gw * 64;
    if (has_resid) {               // resid may alias hout: same-element RMW only
        a0 += resid[base + lane];
        a1 += resid[base + lane + 32];
    }
    hout[base + lane]      = a0;
    hout[base + lane + 32] = a1;
}

// ------------------------------------------- sparse aggregation + log_softmax, M=40
__global__ void agg40_kernel(const float* __restrict__ sup,
                             const float* __restrict__ bias,
                             float* __restrict__ out) {
    int gw   = (blockIdx.x * blockDim.x + threadIdx.x) >> 5;
    int lane = threadIdx.x & 31;
    if (gw >= NNODES) return;
    int e   = g_rowptr[gw];
    int end = g_rowptr[gw + 1];
    float a0 = 0.f, a1 = 0.f;
    for (; e + 4 <= end; e += 4) {
        int2 e0 = g_edge[e], e1 = g_edge[e + 1], e2 = g_edge[e + 2], e3 = g_edge[e + 3];
        const float* p0 = sup + (size_t)e0.x * 40;
        const float* p1 = sup + (size_t)e1.x * 40;
        const float* p2 = sup + (size_t)e2.x * 40;
        const float* p3 = sup + (size_t)e3.x * 40;
        float w0 = __int_as_float(e0.y), w1 = __int_as_float(e1.y);
        float w2 = __int_as_float(e2.y), w3 = __int_as_float(e3.y);
        a0 = fmaf(p0[lane], w0, a0);
        a0 = fmaf(p1[lane], w1, a0);
        a0 = fmaf(p2[lane], w2, a0);
        a0 = fmaf(p3[lane], w3, a0);
        if (lane < 8) {
            a1 = fmaf(p0[32 + lane], w0, a1);
            a1 = fmaf(p1[32 + lane], w1, a1);
            a1 = fmaf(p2[32 + lane], w2, a1);
            a1 = fmaf(p3[32 + lane], w3, a1);
        }
    }
    for (; e < end; e++) {
        int2 ed = g_edge[e];
        const float* p = sup + (size_t)ed.x * 40;
        float w = __int_as_float(ed.y);
        a0 = fmaf(p[lane], w, a0);
        if (lane < 8) a1 = fmaf(p[32 + lane], w, a1);
    }
    a0 += bias[lane];
    if (lane < 8) a1 += bias[32 + lane];

    // log_softmax over 40 features distributed over the warp
    float m = a0;
    if (lane < 8) m = fmaxf(m, a1);
#pragma unroll
    for (int o = 16; o; o >>= 1) m = fmaxf(m, __shfl_xor_sync(0xffffffffu, m, o));
    float ssum = __expf(a0 - m) + ((lane < 8) ? __expf(a1 - m) : 0.f);
#pragma unroll
    for (int o = 16; o; o >>= 1) ssum += __shfl_xor_sync(0xffffffffu, ssum, o);
    float L = m + __logf(ssum);

    out[(size_t)gw * 40 + lane] = a0 - L;
    if (lane < 8) out[(size_t)gw * 40 + 32 + lane] = a1 - L;
}

// ---------------------------------------------------------------- launch
extern "C" void kernel_launch(void* const* d_in, const int* in_sizes, int n_in,
                              void* d_out, int out_size) {
    const float* x   = (const float*)d_in[0];
    const int*   src = (const int*)d_in[1];
    const int*   tgt = (const int*)d_in[2];
    const float* mw  = (const float*)d_in[3];
    const float* W0  = (const float*)d_in[4];  const float* b0 = (const float*)d_in[5];
    const float* W1  = (const float*)d_in[6];  const float* b1 = (const float*)d_in[7];
    const float* W2  = (const float*)d_in[8];  const float* b2 = (const float*)d_in[9];
    const float* W3  = (const float*)d_in[10]; const float* b3 = (const float*)d_in[11];
    float* out = (float*)d_out;

    // smem sizes (same footprint as round-1: Wp is K*M*4 bytes)
    const int S0 = (128 * 64 + 64 * (128 + 4)) * 4;  // 66560
    const int S1 = (64 * 64 + 64 * (64 + 4)) * 4;    // 33792
    const int S3 = (64 * 40 + 64 * (64 + 4)) * 4;    // 27648
    cudaFuncSetAttribute(gemm3_kernel<128, 64>, cudaFuncAttributeMaxDynamicSharedMemorySize, S0);
    cudaFuncSetAttribute(gemm3_kernel<64, 64>,  cudaFuncAttributeMaxDynamicSharedMemorySize, S1);
    cudaFuncSetAttribute(gemm3_kernel<64, 40>,  cudaFuncAttributeMaxDynamicSharedMemorySize, S3);

    void* p;
    cudaGetSymbolAddress(&p, g_support); float* sup = (float*)p;
    cudaGetSymbolAddress(&p, g_h);       float* h   = (float*)p;

    // ---- CSR build (once per call, reused by 4 layers) ----
    zero_counts_kernel<<<(NNODES + 255) / 256, 256>>>();
    hist_kernel<<<(NEDGES + 255) / 256, 256>>>(tgt);
    scan_kernel<<<1, 1024>>>();
    scatter_kernel<<<(NEDGES + 255) / 256, 256>>>(src, tgt, mw);

    const int gblocks = (NNODES + 63) / 64;
    const int ablocks = ((NNODES * 32) + 255) / 256;

    // layer 0: h = relu(A @ (x W0) + b0)
    gemm3_kernel<128, 64><<<gblocks, dim3(16, 16), S0>>>(x, W0, sup, NNODES);
    agg64_kernel<<<ablocks, 256>>>(sup, b0, h, nullptr, 0);
    // layer 1: h = relu(A @ (h W1) + b1) + h
    gemm3_kernel<64, 64><<<gblocks, dim3(16, 16), S1>>>(h, W1, sup, NNODES);
    agg64_kernel<<<ablocks, 256>>>(sup, b1, h, h, 1);
    // layer 2
    gemm3_kernel<64, 64><<<gblocks, dim3(16, 16), S1>>>(h, W2, sup, NNODES);
    agg64_kernel<<<ablocks, 256>>>(sup, b2, h, h, 1);
    // layer 3: out = log_softmax(A @ (h W3) + b3)
    gemm3_kernel<64, 40><<<gblocks, dim3(10, 16), S3>>>(h, W3, sup, NNODES);
    agg40_kernel<<<ablocks, 256>>>(sup, b3, out);
}